// round 13
// baseline (speedup 1.0000x reference)
#include <cuda_runtime.h>
#include <cstdint>
#include <math.h>

// NT_Xent collapsed: neg_n = (r_n/||r_n||) . S / T,  S = sum_m mem_m/||mem_m||.
// One persistent kernel, grid = 148 x 512 (1 block/SM, all co-resident).
// Phase 1: EXACT transplant of R1's measured-best loop (2564 GB/s standalone):
//   512 threads, strided warp rows (gw + k*W), guarded 4-deep batches, ~40 regs.
// pos-part of loss precomputed before grid-sync (independent of S).
// grid-sync; Phase 2: rebuild S in parallel, finish loss, last block -> mean.
// All reductions are fixed-order trees -> deterministic.

#define D      128
#define DV     32             // float4 per row
#define GRID   148
#define T      512
#define NW     16             // warps per block
#define INV_T  10.0f
#define EPSN   1e-8f
#define EPS2   (1e-8f * 1e-8f)

__device__ float        g_partialS[GRID * D];
__device__ float        g_partialLoss[GRID];
__device__ unsigned int g_cnt1 = 0;
__device__ unsigned int g_cnt2 = 0;

__device__ __forceinline__ float warp_sum(float v) {
    #pragma unroll
    for (int o = 16; o > 0; o >>= 1) v += __shfl_xor_sync(0xffffffffu, v, o);
    return v;
}
__device__ __forceinline__ float dot4(float4 a, float4 b) {
    return a.x * b.x + a.y * b.y + a.z * b.z + a.w * b.w;
}

__global__ __launch_bounds__(T)
void fused_ntxent_kernel(const float4* __restrict__ mem, int M,
                         const float4* __restrict__ real,
                         const float4* __restrict__ pert, int N,
                         float* __restrict__ out) {
    __shared__ float4 sacc[NW][32];      // 8KB
    __shared__ float  Sq[4][D];          // 2KB
    __shared__ float  S[D];
    __shared__ float  wsum[NW];
    __shared__ int    islast;

    const int tid  = threadIdx.x;
    const int w    = tid >> 5;
    const int lane = tid & 31;
    const int bid  = blockIdx.x;
    const int gw   = bid * NW + w;       // global warp id
    const int W    = GRID * NW;          // 2368 warps

    // ========== Phase 1: R1's exact loop shape (guarded 4-deep batches) ==========
    float4 acc = make_float4(0.f, 0.f, 0.f, 0.f);

    const int iters = (M + W - 1) / W;   // rows per warp (ceil)
    #pragma unroll 1
    for (int k = 0; k < iters; k += 4) {
        float4 v[4];
        #pragma unroll
        for (int u = 0; u < 4; u++) {
            int m = gw + (k + u) * W;
            v[u] = (m < M) ? mem[(size_t)m * DV + lane]
                           : make_float4(0.f, 0.f, 0.f, 0.f);
        }
        #pragma unroll
        for (int u = 0; u < 4; u++) {
            float s = dot4(v[u], v[u]);
            s = warp_sum(s);
            float inv = rsqrtf(fmaxf(s, EPS2));  // == 1/max(sqrt(s),EPS); 0-row -> 0
            acc.x += v[u].x * inv;
            acc.y += v[u].y * inv;
            acc.z += v[u].z * inv;
            acc.w += v[u].w * inv;
        }
    }

    sacc[w][lane] = acc;
    __syncthreads();
    if (tid < D) {
        float s = 0.f;
        #pragma unroll
        for (int ww = 0; ww < NW; ww++)
            s += ((const float*)sacc[ww])[tid];
        g_partialS[bid * D + tid] = s;
    }
    __threadfence();
    __syncthreads();
    if (tid == 0) atomicAdd(&g_cnt1, 1u);

    // ===== pos-part of the loss (independent of S): overlap with stragglers =====
    const int n = w * GRID + bid;        // each n in [0,N) exactly once (N=1024)
    float4 rv = make_float4(0.f, 0.f, 0.f, 0.f);
    float  pos = 0.f, rn = 1.f;
    if (n < N) {
        rv = real[(size_t)n * DV + lane];
        float4 pv = pert[(size_t)n * DV + lane];
        float rr = warp_sum(dot4(rv, rv));
        float pp = warp_sum(dot4(pv, pv));
        float rp = warp_sum(dot4(rv, pv));
        rn = fmaxf(sqrtf(rr), EPSN);
        float pn = fmaxf(sqrtf(pp), EPSN);
        pos = rp / (rn * pn) * INV_T;
    }

    // ================= grid sync =================
    if (tid == 0) {
        while (*((volatile unsigned int*)&g_cnt1) != GRID) { }
        __threadfence();
    }
    __syncthreads();

    // ================= Phase 2a: rebuild S (parallel, fixed order) =================
    {
        const int col = tid & (D - 1);
        const int q   = tid >> 7;            // 0..3
        float s = 0.f;
        #pragma unroll 4
        for (int b = q; b < GRID; b += 4)
            s += g_partialS[b * D + col];
        Sq[q][col] = s;
    }
    __syncthreads();
    if (tid < D) {
        float t = 0.f;
        #pragma unroll
        for (int j = 0; j < 4; j++) t += Sq[j][tid];
        S[tid] = t;
    }
    __syncthreads();

    const float4 s4 = ((const float4*)S)[lane];

    // ================= Phase 2b: finish loss (needs S) =================
    float lsum = 0.f;
    if (n < N) {
        float rs = warp_sum(dot4(rv, s4));
        if (lane == 0) {
            float neg = rs / rn * INV_T;
            float mx  = fmaxf(pos, neg);
            float lse = mx + logf(expf(pos - mx) + expf(neg - mx));
            lsum = lse - pos;                // -log_softmax[0]
        }
    }
    if (lane == 0) wsum[w] = lsum;
    __syncthreads();

    if (tid == 0) {
        float b = 0.f;
        #pragma unroll
        for (int ww = 0; ww < NW; ww++) b += wsum[ww];
        g_partialLoss[bid] = b;
        __threadfence();
        unsigned int ret = atomicAdd(&g_cnt2, 1u);
        islast = (ret == GRID - 1) ? 1 : 0;
    }
    __syncthreads();

    if (islast && w == 0) {
        __threadfence();
        float v = 0.f;
        #pragma unroll
        for (int j = 0; j < 5; j++) {
            int i = lane + 32 * j;
            if (i < GRID) v += g_partialLoss[i];
        }
        v = warp_sum(v);
        if (lane == 0) {
            out[0] = v / (float)N;
            g_cnt1 = 0;
            g_cnt2 = 0;
        }
    }
}

extern "C" void kernel_launch(void* const* d_in, const int* in_sizes, int n_in,
                              void* d_out, int out_size) {
    const float4* real = (const float4*)d_in[0];
    const float4* pert = (const float4*)d_in[1];
    const float4* mem  = (const float4*)d_in[2];
    int N = in_sizes[0] / D;
    int M = in_sizes[2] / D;

    fused_ntxent_kernel<<<GRID, T>>>(mem, M, real, pert, N, (float*)d_out);
}

// round 14
// speedup vs baseline: 1.0363x; 1.0363x over previous
#include <cuda_runtime.h>
#include <cstdint>
#include <math.h>

// NT_Xent collapsed: neg_n = (r_n/||r_n||) . S / T,  S = sum_m mem_m/||mem_m||.
// TWO kernels (graph-captured back to back):
//  K1: verbatim R1 bank-reduce (512thr x 148 blocks, measured 2564 GB/s,
//      regs=40) -> g_partialS[148][128]. Kept isolated so ptxas reproduces
//      R1's load schedule (fusing it regressed codegen to regs=32/1575 GB/s).
//  K2: one kernel for the whole tail: rebuild S in parallel, one loss row per
//      warp (64 blocks x 16 warps = N), per-block partial, last-arriving block
//      reduces 64 partials -> mean -> out, resets counter (graph-replay safe).
// All reductions are fixed-order trees -> deterministic.

#define D      128
#define DV     32            // float4 per row
#define B1     148
#define T1     512
#define NW1    (T1 / 32)     // 16 warps
#define B2     64
#define T2     512
#define NW2    (T2 / 32)     // 16 warps
#define INV_T  10.0f
#define EPSN   1e-8f

__device__ float        g_partialS[B1 * D];
__device__ float        g_partialLoss[B2];
__device__ unsigned int g_cnt = 0;

__device__ __forceinline__ float warp_sum(float v) {
    #pragma unroll
    for (int o = 16; o > 0; o >>= 1) v += __shfl_xor_sync(0xffffffffu, v, o);
    return v;
}
__device__ __forceinline__ float dot4(float4 a, float4 b) {
    return a.x * b.x + a.y * b.y + a.z * b.z + a.w * b.w;
}

// ---------------- K1: memory-bank reduction (VERBATIM R1) ----------------
__global__ __launch_bounds__(T1) void bank_reduce_kernel(const float4* __restrict__ mem, int M) {
    const int tid  = threadIdx.x;
    const int w    = tid >> 5;
    const int lane = tid & 31;
    const int gw   = blockIdx.x * NW1 + w;     // global warp id
    const int W    = B1 * NW1;                 // total warps

    float4 acc = make_float4(0.f, 0.f, 0.f, 0.f);

    const int iters = (M + W - 1) / W;         // rows per warp (ceil)
    for (int k = 0; k < iters; k += 4) {
        float4 v[4];
        #pragma unroll
        for (int u = 0; u < 4; u++) {
            int m = gw + (k + u) * W;
            v[u] = (m < M) ? mem[(size_t)m * DV + lane]
                           : make_float4(0.f, 0.f, 0.f, 0.f);
        }
        #pragma unroll
        for (int u = 0; u < 4; u++) {
            float s = v[u].x * v[u].x + v[u].y * v[u].y
                    + v[u].z * v[u].z + v[u].w * v[u].w;
            s = warp_sum(s);
            float inv = 1.0f / fmaxf(sqrtf(s), EPSN);  // zero rows contribute 0
            acc.x += v[u].x * inv;
            acc.y += v[u].y * inv;
            acc.z += v[u].z * inv;
            acc.w += v[u].w * inv;
        }
    }

    __shared__ float4 sacc[NW1][32];
    sacc[w][lane] = acc;
    __syncthreads();

    if (tid < D) {
        float s = 0.f;
        #pragma unroll
        for (int ww = 0; ww < NW1; ww++)
            s += ((const float*)sacc[ww])[tid];
        g_partialS[blockIdx.x * D + tid] = s;
    }
}

// ---------------- K2: S rebuild + per-row loss + final mean ----------------
__global__ __launch_bounds__(T2) void loss_kernel(const float4* __restrict__ real,
                                                  const float4* __restrict__ pert,
                                                  int N, float* __restrict__ out) {
    __shared__ float Sq[4][D];
    __shared__ float S[D];
    __shared__ float wsum[NW2];
    __shared__ int   islast;

    const int tid  = threadIdx.x;
    const int w    = tid >> 5;
    const int lane = tid & 31;
    const int bid  = blockIdx.x;

    // rebuild S: 4-way split over the 148 partials, fixed order per column
    {
        const int col = tid & (D - 1);
        const int q   = tid >> 7;            // 0..3
        float s = 0.f;
        #pragma unroll 4
        for (int b = q; b < B1; b += 4)
            s += g_partialS[b * D + col];
        Sq[q][col] = s;
    }
    __syncthreads();
    if (tid < D) {
        float t = 0.f;
        #pragma unroll
        for (int j = 0; j < 4; j++) t += Sq[j][tid];
        S[tid] = t;
    }
    __syncthreads();

    const float4 s4 = ((const float4*)S)[lane];

    // one loss row per warp: 64 blocks x 16 warps = 1024 = N
    float lsum = 0.f;
    {
        int n = bid * NW2 + w;
        if (n < N) {
            float4 rv = real[(size_t)n * DV + lane];
            float4 pv = pert[(size_t)n * DV + lane];
            float rr = warp_sum(dot4(rv, rv));
            float pp = warp_sum(dot4(pv, pv));
            float rp = warp_sum(dot4(rv, pv));
            float rs = warp_sum(dot4(rv, s4));
            if (lane == 0) {
                float rn  = fmaxf(sqrtf(rr), EPSN);
                float pn  = fmaxf(sqrtf(pp), EPSN);
                float pos = rp / (rn * pn) * INV_T;
                float neg = rs / rn * INV_T;
                float mx  = fmaxf(pos, neg);
                float lse = mx + logf(expf(pos - mx) + expf(neg - mx));
                lsum = lse - pos;            // -log_softmax[0]
            }
        }
    }
    if (lane == 0) wsum[w] = lsum;
    __syncthreads();

    if (tid == 0) {
        float b = 0.f;
        #pragma unroll
        for (int ww = 0; ww < NW2; ww++) b += wsum[ww];
        g_partialLoss[bid] = b;
        __threadfence();
        unsigned int ret = atomicAdd(&g_cnt, 1u);
        islast = (ret == B2 - 1) ? 1 : 0;
    }
    __syncthreads();

    // last-arriving block: fixed-order 64->1 reduce, write mean, reset counter
    if (islast && w == 0) {
        __threadfence();
        float v = 0.f;
        #pragma unroll
        for (int j = 0; j < B2 / 32; j++)
            v += g_partialLoss[lane + 32 * j];
        v = warp_sum(v);
        if (lane == 0) {
            out[0] = v / (float)N;
            g_cnt = 0;
        }
    }
}

extern "C" void kernel_launch(void* const* d_in, const int* in_sizes, int n_in,
                              void* d_out, int out_size) {
    const float4* real = (const float4*)d_in[0];
    const float4* pert = (const float4*)d_in[1];
    const float4* mem  = (const float4*)d_in[2];
    int N = in_sizes[0] / D;
    int M = in_sizes[2] / D;

    bank_reduce_kernel<<<B1, T1>>>(mem, M);
    loss_kernel<<<B2, T2>>>(real, pert, N, (float*)d_out);
}

// round 15
// speedup vs baseline: 1.1345x; 1.0947x over previous
#include <cuda_runtime.h>
#include <cstdint>
#include <math.h>

// NT_Xent collapsed: neg_n = (r_n/||r_n||) . S / T,  S = sum_m mem_m/||mem_m||.
// TWO kernels (graph-captured back to back):
//  K1: verbatim R1 bank-reduce (512thr x 148 blocks, 2564 GB/s, regs=40)
//      -> g_partialS[148][128]. Isolated so ptxas keeps R1's load schedule.
//  K2: loss tail, restructured for latency overlap:
//      - rv/pv loads issued FIRST (hide behind S rebuild)
//      - S rebuild fully unrolled (37 loads in flight; 148 = 4*37 exactly)
//      - one loss row per warp (64 x 16 = N), last-arriving block -> mean,
//        resets counter (graph-replay safe).
// All reductions are fixed-order trees -> deterministic.

#define D      128
#define DV     32            // float4 per row
#define B1     148
#define T1     512
#define NW1    (T1 / 32)     // 16 warps
#define B2     64
#define T2     512
#define NW2    (T2 / 32)     // 16 warps
#define INV_T  10.0f
#define EPSN   1e-8f

__device__ float        g_partialS[B1 * D];
__device__ float        g_partialLoss[B2];
__device__ unsigned int g_cnt = 0;

__device__ __forceinline__ float warp_sum(float v) {
    #pragma unroll
    for (int o = 16; o > 0; o >>= 1) v += __shfl_xor_sync(0xffffffffu, v, o);
    return v;
}
__device__ __forceinline__ float dot4(float4 a, float4 b) {
    return a.x * b.x + a.y * b.y + a.z * b.z + a.w * b.w;
}

// ---------------- K1: memory-bank reduction (VERBATIM R1) ----------------
__global__ __launch_bounds__(T1) void bank_reduce_kernel(const float4* __restrict__ mem, int M) {
    const int tid  = threadIdx.x;
    const int w    = tid >> 5;
    const int lane = tid & 31;
    const int gw   = blockIdx.x * NW1 + w;     // global warp id
    const int W    = B1 * NW1;                 // total warps

    float4 acc = make_float4(0.f, 0.f, 0.f, 0.f);

    const int iters = (M + W - 1) / W;         // rows per warp (ceil)
    for (int k = 0; k < iters; k += 4) {
        float4 v[4];
        #pragma unroll
        for (int u = 0; u < 4; u++) {
            int m = gw + (k + u) * W;
            v[u] = (m < M) ? mem[(size_t)m * DV + lane]
                           : make_float4(0.f, 0.f, 0.f, 0.f);
        }
        #pragma unroll
        for (int u = 0; u < 4; u++) {
            float s = v[u].x * v[u].x + v[u].y * v[u].y
                    + v[u].z * v[u].z + v[u].w * v[u].w;
            s = warp_sum(s);
            float inv = 1.0f / fmaxf(sqrtf(s), EPSN);  // zero rows contribute 0
            acc.x += v[u].x * inv;
            acc.y += v[u].y * inv;
            acc.z += v[u].z * inv;
            acc.w += v[u].w * inv;
        }
    }

    __shared__ float4 sacc[NW1][32];
    sacc[w][lane] = acc;
    __syncthreads();

    if (tid < D) {
        float s = 0.f;
        #pragma unroll
        for (int ww = 0; ww < NW1; ww++)
            s += ((const float*)sacc[ww])[tid];
        g_partialS[blockIdx.x * D + tid] = s;
    }
}

// ---------------- K2: prefetch rows + unrolled S rebuild + loss ----------------
__global__ __launch_bounds__(T2) void loss_kernel(const float4* __restrict__ real,
                                                  const float4* __restrict__ pert,
                                                  int N, float* __restrict__ out) {
    __shared__ float Sq[4][D];
    __shared__ float S[D];
    __shared__ float wsum[NW2];
    __shared__ int   islast;

    const int tid  = threadIdx.x;
    const int w    = tid >> 5;
    const int lane = tid & 31;
    const int bid  = blockIdx.x;
    const int n    = bid * NW2 + w;          // 64*16 = 1024 rows, each once

    // ---- 1) issue per-row loads FIRST (latency hides behind S rebuild) ----
    float4 rv = make_float4(0.f, 0.f, 0.f, 0.f);
    float4 pv = make_float4(0.f, 0.f, 0.f, 0.f);
    if (n < N) {
        rv = real[(size_t)n * DV + lane];
        pv = pert[(size_t)n * DV + lane];
    }

    // ---- 2) rebuild S: fully unrolled 37-trip loop (148 = 4*37) ----
    {
        const int col = tid & (D - 1);
        const int q   = tid >> 7;            // 0..3
        float s = 0.f;
        #pragma unroll
        for (int j = 0; j < B1 / 4; j++)     // 37 independent loads in flight
            s += g_partialS[(q + 4 * j) * D + col];
        Sq[q][col] = s;
    }
    __syncthreads();
    if (tid < D) {
        float t = 0.f;
        #pragma unroll
        for (int j = 0; j < 4; j++) t += Sq[j][tid];
        S[tid] = t;
    }
    __syncthreads();

    const float4 s4 = ((const float4*)S)[lane];

    // ---- 3) loss: 4 independent butterflies (ILP) ----
    float lsum = 0.f;
    if (n < N) {
        float rr = dot4(rv, rv);
        float pp = dot4(pv, pv);
        float rp = dot4(rv, pv);
        float rs = dot4(rv, s4);
        #pragma unroll
        for (int o = 16; o > 0; o >>= 1) {
            rr += __shfl_xor_sync(0xffffffffu, rr, o);
            pp += __shfl_xor_sync(0xffffffffu, pp, o);
            rp += __shfl_xor_sync(0xffffffffu, rp, o);
            rs += __shfl_xor_sync(0xffffffffu, rs, o);
        }
        if (lane == 0) {
            float rn  = fmaxf(sqrtf(rr), EPSN);
            float pn  = fmaxf(sqrtf(pp), EPSN);
            float pos = rp / (rn * pn) * INV_T;
            float neg = rs / rn * INV_T;
            float mx  = fmaxf(pos, neg);
            float lse = mx + logf(expf(pos - mx) + expf(neg - mx));
            lsum = lse - pos;                // -log_softmax[0]
        }
    }
    if (lane == 0) wsum[w] = lsum;
    __syncthreads();

    if (tid == 0) {
        float b = 0.f;
        #pragma unroll
        for (int ww = 0; ww < NW2; ww++) b += wsum[ww];
        g_partialLoss[bid] = b;
        __threadfence();
        unsigned int ret = atomicAdd(&g_cnt, 1u);
        islast = (ret == B2 - 1) ? 1 : 0;
    }
    __syncthreads();

    // last-arriving block: fixed-order 64->1 reduce, write mean, reset counter
    if (islast && w == 0) {
        __threadfence();
        float v = 0.f;
        #pragma unroll
        for (int j = 0; j < B2 / 32; j++)
            v += g_partialLoss[lane + 32 * j];
        v = warp_sum(v);
        if (lane == 0) {
            out[0] = v / (float)N;
            g_cnt = 0;
        }
    }
}

extern "C" void kernel_launch(void* const* d_in, const int* in_sizes, int n_in,
                              void* d_out, int out_size) {
    const float4* real = (const float4*)d_in[0];
    const float4* pert = (const float4*)d_in[1];
    const float4* mem  = (const float4*)d_in[2];
    int N = in_sizes[0] / D;
    int M = in_sizes[2] / D;

    bank_reduce_kernel<<<B1, T1>>>(mem, M);
    loss_kernel<<<B2, T2>>>(real, pert, N, (float*)d_out);
}